// round 8
// baseline (speedup 1.0000x reference)
#include <cuda_runtime.h>
#include <cuda_bf16.h>
#include <cstdint>

// B=1024, S=200, D=64, C=256
// Inputs: rq_item_embeddings f32 [B,S,D], labels i32 [B,S], attention_mask i32 [B,S]
// Output (float32, concatenated):
//   [0 .. B*C*D)             cluster_emb
//   [B*C*D .. +B*C*S)        cluster_mask (0.0f/1.0f)
//
// Grid = B*8: each CTA owns one batch b and a 32-cluster range.
// Warp 0 runs the latency-bound label/count/scan chain while warps 1-7
// stream the mask zero-fill; only 2 block-wide barriers remain.

namespace {
constexpr int B = 1024;
constexpr int S = 200;
constexpr int D = 64;
constexpr int C = 256;
constexpr int SPLIT = 8;
constexpr int CPART = C / SPLIT;      // 32 clusters per CTA
}

__global__ __launch_bounds__(256) void s3rec_fused_kernel(
    const float* __restrict__ x,       // [B,S,D]
    const int*   __restrict__ labels,  // [B,S]
    const int*   __restrict__ amask,   // [B,S]
    float*       __restrict__ out)
{
    __shared__ int lab[208];        // fused label+mask (-1 = masked out)
    __shared__ int cnt[CPART];      // per-local-cluster member count
    __shared__ int startA[CPART];   // exclusive prefix
    __shared__ int cursor[CPART];   // scatter cursors
    __shared__ int order[208];      // s-indices sorted by local cluster

    const int b    = blockIdx.x >> 3;
    const int part = blockIdx.x & 7;      // cluster octant
    const int tid  = threadIdx.x;
    const int w    = tid >> 5;
    const int lane = tid & 31;
    const int cBase = part * CPART;

    float* maskOutP = out + (size_t)B * C * D
                          + (size_t)b * C * S
                          + (size_t)cBase * S;

    // ---- Phase 0 (specialized): warp 0 = labels/counts/scan;
    //                             warps 1-7 = mask zero-fill -------------
    if (w == 0) {
        // zero counts (one per lane)
        cnt[lane] = 0;
        __syncwarp();
        // load 200 labels: lane covers s = lane, lane+32, ... (7 iters)
        #pragma unroll
        for (int s = lane; s < S; s += 32) {
            int m = __ldg(amask + b * S + s);
            int l = m ? __ldg(labels + b * S + s) : -1;
            lab[s] = l;
            int cl = l - cBase;
            if (cl >= 0 && cl < CPART) atomicAdd(&cnt[cl], 1);
        }
        __syncwarp();
        // exclusive scan over 32 counts (single warp, shfl)
        const int v = cnt[lane];
        int incl = v;
        #pragma unroll
        for (int off = 1; off < 32; off <<= 1) {
            int t = __shfl_up_sync(0xFFFFFFFFu, incl, off);
            if (lane >= off) incl += t;
        }
        const int st = incl - v;
        startA[lane] = st;
        cursor[lane] = st;
    } else {
        // zero-fill the 32-cluster mask slab: 1600 quads over 224 threads
        const float4 z4 = make_float4(0.f, 0.f, 0.f, 0.f);
        float4* mq = reinterpret_cast<float4*>(maskOutP);
        constexpr int NQ = CPART * S / 4;   // 1600
        const int t2 = tid - 32;            // 0..223
        #pragma unroll 8
        for (int i = t2; i < NQ; i += 224)
            __stcs(mq + i, z4);
    }
    __syncthreads();

    // ---- Phase 1: ones-scatter + order-scatter (all threads) ----------
    if (tid < S) {
        const int cl = lab[tid] - cBase;
        if (cl >= 0 && cl < CPART) {
            int p = atomicAdd(&cursor[cl], 1);
            order[p] = tid;
            maskOutP[cl * S + tid] = 1.0f;   // ordered after zero-fill barrier
        }
    }
    __syncthreads();

    // ---- Phase 2: gather; half-warp per cluster, float4 lanes ---------
    // Each warp handles 2 clusters per pass (lanes 0-15 / 16-31),
    // 16 lanes x float4 = one D row. 2 passes x 16 = 32 clusters.
    {
        const float* xb = x + (size_t)b * S * D;
        float* embOut   = out + (size_t)b * C * D;
        const int hw  = lane >> 4;         // half-warp id (0/1)
        const int l16 = lane & 15;

        #pragma unroll
        for (int pass = 0; pass < CPART / 16; pass++) {   // 2 passes
            const int cLocal = pass * 16 + w * 2 + hw;
            const int k  = cnt[cLocal];
            const int s0 = startA[cLocal];
            float4 acc = make_float4(0.f, 0.f, 0.f, 0.f);
            if (k > 0) {
                int sCur = order[s0];
                for (int j = 0; j < k; j++) {
                    const int sNext = (j + 1 < k) ? order[s0 + j + 1] : 0;
                    const float4 vv =
                        reinterpret_cast<const float4*>(xb + sCur * D)[l16];
                    acc.x += vv.x; acc.y += vv.y; acc.z += vv.z; acc.w += vv.w;
                    sCur = sNext;
                }
                const float inv = 1.0f / (float)k;
                acc.x *= inv; acc.y *= inv; acc.z *= inv; acc.w *= inv;
            }
            __stcs(reinterpret_cast<float4*>(embOut + (cBase + cLocal) * D) + l16, acc);
        }
    }
}

extern "C" void kernel_launch(void* const* d_in, const int* in_sizes, int n_in,
                              void* d_out, int out_size)
{
    const float* x      = (const float*)d_in[0];
    const int*   labels = (const int*)d_in[1];
    const int*   amask  = (const int*)d_in[2];
    float*       out    = (float*)d_out;

    s3rec_fused_kernel<<<B * SPLIT, 256>>>(x, labels, amask, out);
}

// round 9
// speedup vs baseline: 1.0854x; 1.0854x over previous
#include <cuda_runtime.h>
#include <cuda_bf16.h>
#include <cstdint>

// B=1024, S=200, D=64, C=256
// Inputs: rq_item_embeddings f32 [B,S,D], labels i32 [B,S], attention_mask i32 [B,S]
// Output (float32, concatenated):
//   [0 .. B*C*D)             cluster_emb
//   [B*C*D .. +B*C*S)        cluster_mask (0.0f/1.0f)
//
// Grid = B*8: each CTA owns one batch b and a 32-cluster range.
// Direct smem bucketing: one atomicAdd yields both count and slot, so the
// prefix scan and two block barriers disappear (2 barriers total).

namespace {
constexpr int B = 1024;
constexpr int S = 200;
constexpr int D = 64;
constexpr int C = 256;
constexpr int SPLIT = 8;
constexpr int CPART = C / SPLIT;      // 32 clusters per CTA
}

__global__ __launch_bounds__(256) void s3rec_fused_kernel(
    const float* __restrict__ x,       // [B,S,D]
    const int*   __restrict__ labels,  // [B,S]
    const int*   __restrict__ amask,   // [B,S]
    float*       __restrict__ out)
{
    __shared__ int lab[208];            // fused label+mask (-1 = masked out)
    __shared__ int cnt[CPART];          // per-local-cluster member count
    __shared__ int bucket[CPART][S];    // member s-indices, 25.6 KB

    const int b    = blockIdx.x >> 3;
    const int part = blockIdx.x & 7;    // cluster octant
    const int tid  = threadIdx.x;
    const int w    = tid >> 5;
    const int lane = tid & 31;
    const int cBase = part * CPART;

    float* maskOutP = out + (size_t)B * C * D
                          + (size_t)b * C * S
                          + (size_t)cBase * S;

    // ---- Phase 0: wide label load + counts zero + mask zero-fill ------
    int myLab = -1;
    if (tid < S) {
        int m = __ldg(amask + b * S + tid);
        myLab = m ? __ldg(labels + b * S + tid) : -1;
        lab[tid] = myLab;
    }
    if (tid < CPART) cnt[tid] = 0;

    {
        const float4 z4 = make_float4(0.f, 0.f, 0.f, 0.f);
        float4* mq = reinterpret_cast<float4*>(maskOutP);
        constexpr int NQ = CPART * S / 4;   // 1600 quads, 6.25/thread
        #pragma unroll 7
        for (int i = tid; i < NQ; i += 256)
            __stcs(mq + i, z4);
    }
    __syncthreads();

    // ---- Phase 1: bucket scatter + ones write (one atomic does both) --
    {
        const int cl = myLab - cBase;
        if (cl >= 0 && cl < CPART) {
            int p = atomicAdd(&cnt[cl], 1);
            bucket[cl][p] = tid;
            maskOutP[cl * S + tid] = 1.0f;   // ordered after zero-fill barrier
        }
    }
    __syncthreads();

    // ---- Phase 2: gather; half-warp per cluster, float4 lanes ---------
    // Each warp handles 2 clusters per pass (lanes 0-15 / 16-31),
    // 16 lanes x float4 = one D row. 2 passes x 16 = 32 clusters.
    {
        const float* xb = x + (size_t)b * S * D;
        float* embOut   = out + (size_t)b * C * D;
        const int hw  = lane >> 4;          // half-warp id (0/1)
        const int l16 = lane & 15;

        #pragma unroll
        for (int pass = 0; pass < CPART / 16; pass++) {   // 2 passes
            const int cLocal = pass * 16 + w * 2 + hw;
            const int k = cnt[cLocal];
            float4 acc = make_float4(0.f, 0.f, 0.f, 0.f);
            if (k > 0) {
                int sCur = bucket[cLocal][0];
                for (int j = 0; j < k; j++) {
                    const int sNext = (j + 1 < k) ? bucket[cLocal][j + 1] : 0;
                    const float4 vv =
                        reinterpret_cast<const float4*>(xb + sCur * D)[l16];
                    acc.x += vv.x; acc.y += vv.y; acc.z += vv.z; acc.w += vv.w;
                    sCur = sNext;
                }
                const float inv = 1.0f / (float)k;
                acc.x *= inv; acc.y *= inv; acc.z *= inv; acc.w *= inv;
            }
            __stcs(reinterpret_cast<float4*>(embOut + (cBase + cLocal) * D) + l16, acc);
        }
    }
}

extern "C" void kernel_launch(void* const* d_in, const int* in_sizes, int n_in,
                              void* d_out, int out_size)
{
    const float* x      = (const float*)d_in[0];
    const int*   labels = (const int*)d_in[1];
    const int*   amask  = (const int*)d_in[2];
    float*       out    = (float*)d_out;

    s3rec_fused_kernel<<<B * SPLIT, 256>>>(x, labels, amask, out);
}

// round 10
// speedup vs baseline: 1.0957x; 1.0095x over previous
#include <cuda_runtime.h>
#include <cuda_bf16.h>
#include <cstdint>

// B=1024, S=200, D=64, C=256
// Inputs: rq_item_embeddings f32 [B,S,D], labels i32 [B,S], attention_mask i32 [B,S]
// Output (float32, concatenated):
//   [0 .. B*C*D)             cluster_emb
//   [B*C*D .. +B*C*S)        cluster_mask (0.0f/1.0f)
//
// Grid = B*8: each CTA owns one batch b and a 32-cluster range.
// Direct smem bucketing (uint8 s-indices): one atomicAdd yields both count
// and slot, 2 block barriers total, ~7.5 KB smem -> full occupancy.

namespace {
constexpr int B = 1024;
constexpr int S = 200;
constexpr int D = 64;
constexpr int C = 256;
constexpr int SPLIT = 8;
constexpr int CPART = C / SPLIT;      // 32 clusters per CTA
}

__global__ __launch_bounds__(256) void s3rec_fused_kernel(
    const float* __restrict__ x,       // [B,S,D]
    const int*   __restrict__ labels,  // [B,S]
    const int*   __restrict__ amask,   // [B,S]
    float*       __restrict__ out)
{
    __shared__ int cnt[CPART];                    // per-local-cluster count
    __shared__ unsigned char bucket[CPART][S];    // member s-indices, 6.4 KB

    const int b    = blockIdx.x >> 3;
    const int part = blockIdx.x & 7;    // cluster octant
    const int tid  = threadIdx.x;
    const int w    = tid >> 5;
    const int lane = tid & 31;
    const int cBase = part * CPART;

    float* maskOutP = out + (size_t)B * C * D
                          + (size_t)b * C * S
                          + (size_t)cBase * S;

    // ---- Phase 0: wide label load + counts zero + mask zero-fill ------
    int myLab = -1;
    if (tid < S) {
        int m = __ldg(amask + b * S + tid);
        myLab = m ? __ldg(labels + b * S + tid) : -1;
    }
    if (tid < CPART) cnt[tid] = 0;

    {
        const float4 z4 = make_float4(0.f, 0.f, 0.f, 0.f);
        float4* mq = reinterpret_cast<float4*>(maskOutP);
        constexpr int NQ = CPART * S / 4;   // 1600 quads, 6.25/thread
        #pragma unroll 7
        for (int i = tid; i < NQ; i += 256)
            __stcs(mq + i, z4);
    }
    __syncthreads();

    // ---- Phase 1: bucket scatter + ones write (one atomic does both) --
    {
        const int cl = myLab - cBase;
        if (cl >= 0 && cl < CPART) {
            int p = atomicAdd(&cnt[cl], 1);
            bucket[cl][p] = (unsigned char)tid;
            maskOutP[cl * S + tid] = 1.0f;   // ordered after zero-fill barrier
        }
    }
    __syncthreads();

    // ---- Phase 2: gather; half-warp per cluster, float4 lanes ---------
    // Each warp handles 2 clusters per pass (lanes 0-15 / 16-31),
    // 16 lanes x float4 = one D row. 2 passes x 16 = 32 clusters.
    {
        const float* xb = x + (size_t)b * S * D;
        float* embOut   = out + (size_t)b * C * D;
        const int hw  = lane >> 4;          // half-warp id (0/1)
        const int l16 = lane & 15;

        #pragma unroll
        for (int pass = 0; pass < CPART / 16; pass++) {   // 2 passes
            const int cLocal = pass * 16 + w * 2 + hw;
            const int k = cnt[cLocal];
            float4 acc = make_float4(0.f, 0.f, 0.f, 0.f);
            if (k > 0) {
                int sCur = bucket[cLocal][0];
                for (int j = 0; j < k; j++) {
                    const int sNext = (j + 1 < k) ? (int)bucket[cLocal][j + 1] : 0;
                    const float4 vv =
                        reinterpret_cast<const float4*>(xb + sCur * D)[l16];
                    acc.x += vv.x; acc.y += vv.y; acc.z += vv.z; acc.w += vv.w;
                    sCur = sNext;
                }
                const float inv = 1.0f / (float)k;
                acc.x *= inv; acc.y *= inv; acc.z *= inv; acc.w *= inv;
            }
            __stcs(reinterpret_cast<float4*>(embOut + (cBase + cLocal) * D) + l16, acc);
        }
    }
}

extern "C" void kernel_launch(void* const* d_in, const int* in_sizes, int n_in,
                              void* d_out, int out_size)
{
    const float* x      = (const float*)d_in[0];
    const int*   labels = (const int*)d_in[1];
    const int*   amask  = (const int*)d_in[2];
    float*       out    = (float*)d_out;

    s3rec_fused_kernel<<<B * SPLIT, 256>>>(x, labels, amask, out);
}